// round 2
// baseline (speedup 1.0000x reference)
#include <cuda_runtime.h>

#define BSZ 4096
#define DIM 128
#define NT  32   // 4096 / 128 tiles per dimension

// Scratch (device globals: no allocation allowed in kernel_launch)
__device__ float g_Zi[BSZ * DIM];   // normalized rows for links[:,0]
__device__ float g_Zj[BSZ * DIM];   // normalized rows for links[:,1]
__device__ float g_sa[BSZ];         // sum exp(logit-20) for row a_i
__device__ float g_sb[BSZ];         // sum exp(logit-20) for row b_i
__device__ float g_diag[BSZ];       // logits_ab[i,i]

__device__ __forceinline__ float ex2f(float x) {
    float y;
    asm("ex2.approx.ftz.f32 %0, %1;" : "=f"(y) : "f"(x));
    return y;
}

// Kernel 1: zero accumulators + gather + L2-normalize the 8192 referenced rows.
// One warp per output row (8192 warps). Handles links dtype int32 OR int64:
// if int64 (values < 2e5, non-negative) every odd 32-bit word is 0; if int32
// the odd words are real indices (P(16 consecutive zeros) ~ 0).
__global__ void gather_norm(const float* __restrict__ emb,
                            const int* __restrict__ links32) {
    int tid  = blockIdx.x * blockDim.x + threadIdx.x;
    if (tid < BSZ) { g_sa[tid] = 0.f; g_sb[tid] = 0.f; }
    int w    = tid >> 5;
    int lane = tid & 31;
    if (w >= 2 * BSZ) return;

    bool is64 = true;
#pragma unroll
    for (int j = 0; j < 16; j++) is64 &= (__ldg(&links32[2 * j + 1]) == 0);

    int row   = w >> 1;
    int which = w & 1;  // 0 -> Zi, 1 -> Zj
    int pos   = 2 * row + which;
    long long src;
    if (is64) src = reinterpret_cast<const long long*>(links32)[pos];
    else      src = (long long)links32[pos];

    const float4* p = reinterpret_cast<const float4*>(emb + (size_t)src * DIM);
    float4 v = p[lane];  // 128 floats = 32 lanes * float4
    float ss = v.x * v.x + v.y * v.y + v.z * v.z + v.w * v.w;
#pragma unroll
    for (int o = 16; o; o >>= 1) ss += __shfl_xor_sync(0xffffffffu, ss, o);
    float inv = 1.0f / fmaxf(sqrtf(ss), 1e-12f);
    float* dst = (which ? g_Zj : g_Zi) + row * DIM;
    reinterpret_cast<float4*>(dst)[lane] =
        make_float4(v.x * inv, v.y * inv, v.z * inv, v.w * inv);
}

// Kernel 2: fused Gram-tile + exp + row/col sum accumulation.
// blockIdx.y: 0 = S_ab (full 32x32 tiles), 1 = S_aa (ti<=tj), 2 = S_bb (ti<=tj).
// 256 threads, each owns an 8x8 micro-tile with 16-strided rows/cols.
__global__ __launch_bounds__(256) void tile_kernel() {
    int type = blockIdx.y;
    int ti = blockIdx.x >> 5;
    int tj = blockIdx.x & 31;
    if (type != 0 && ti > tj) return;   // symmetric matrices: upper triangle only

    const float* Am = (type == 2) ? g_Zj : g_Zi;
    const float* Bm = (type == 0) ? g_Zj : Am;
    const int ib = ti * 128, jb = tj * 128;

    __shared__ float As[32][129];   // [k][row], pitch 129 => conflict-free
    __shared__ float Bs[32][129];

    int t  = threadIdx.x;
    int tx = t & 15, ty = t >> 4;

    float acc[8][8];
#pragma unroll
    for (int v = 0; v < 8; v++)
#pragma unroll
        for (int u = 0; u < 8; u++) acc[v][u] = 0.f;

    for (int kc = 0; kc < 4; kc++) {
#pragma unroll
        for (int it = 0; it < 4; it++) {
            int idx = t + 256 * it;
            int row = idx >> 3, kq = idx & 7;
            float4 av = reinterpret_cast<const float4*>(Am + (size_t)(ib + row) * DIM + kc * 32)[kq];
            float4 bv = reinterpret_cast<const float4*>(Bm + (size_t)(jb + row) * DIM + kc * 32)[kq];
            As[kq * 4 + 0][row] = av.x; As[kq * 4 + 1][row] = av.y;
            As[kq * 4 + 2][row] = av.z; As[kq * 4 + 3][row] = av.w;
            Bs[kq * 4 + 0][row] = bv.x; Bs[kq * 4 + 1][row] = bv.y;
            Bs[kq * 4 + 2][row] = bv.z; Bs[kq * 4 + 3][row] = bv.w;
        }
        __syncthreads();
#pragma unroll
        for (int k = 0; k < 32; k++) {
            float a_[8], b_[8];
#pragma unroll
            for (int v = 0; v < 8; v++) a_[v] = As[k][ty + 16 * v];
#pragma unroll
            for (int u = 0; u < 8; u++) b_[u] = Bs[k][tx + 16 * u];
#pragma unroll
            for (int v = 0; v < 8; v++)
#pragma unroll
                for (int u = 0; u < 8; u++)
                    acc[v][u] = fmaf(a_[v], b_[u], acc[v][u]);
        }
        __syncthreads();
    }

    // Epilogue: logit = acc/tau = acc*20; fixed shift of 20 (|cos|<=1).
    // exp(logit-20) = ex2((acc-1)*20*log2e)
    const float SC = 20.0f * 1.4426950408889634f;
    bool dt = (ti == tj);
    float rs[8], cs[8];
#pragma unroll
    for (int v = 0; v < 8; v++) rs[v] = 0.f;
#pragma unroll
    for (int u = 0; u < 8; u++) cs[u] = 0.f;

#pragma unroll
    for (int v = 0; v < 8; v++) {
#pragma unroll
        for (int u = 0; u < 8; u++) {
            float e = ex2f(fmaf(acc[v][u], SC, -SC));
            bool ondiag = dt && (tx == ty) && (u == v);   // global i == j
            if (ondiag) {
                if (type != 0) e = 0.f;                           // aa/bb masked
                else g_diag[ib + ty + 16 * v] = acc[v][u] * 20.0f; // ab diag logit
            }
            rs[v] += e;
            cs[u] += e;
        }
    }

    // Reductions via smem (reuse As storage: 128x17 floats <= 32x129)
    float (*red)[17] = reinterpret_cast<float(*)[17]>(&As[0][0]);

#pragma unroll
    for (int v = 0; v < 8; v++) red[ty + 16 * v][tx] = rs[v];
    __syncthreads();
    if (t < 128) {
        float s = 0.f;
#pragma unroll
        for (int x = 0; x < 16; x++) s += red[t][x];
        float* dst = (type == 2) ? g_sb : g_sa;
        atomicAdd(&dst[ib + t], s);
    }
    __syncthreads();

#pragma unroll
    for (int u = 0; u < 8; u++) red[tx + 16 * u][ty] = cs[u];
    __syncthreads();
    if (t < 128) {
        float s = 0.f;
#pragma unroll
        for (int x = 0; x < 16; x++) s += red[t][x];
        if (type == 0) {
            atomicAdd(&g_sb[jb + t], s);          // S_ba row sums = S_ab col sums
        } else if (ti < tj) {                     // symmetry: col sums -> block tj rows
            float* dst = (type == 1) ? g_sa : g_sb;
            atomicAdd(&dst[jb + t], s);
        }
    }
}

// Kernel 3: loss = 20 + mean_i [ 0.5*ln2*(log2 sa_i + log2 sb_i) - diag_i ]
__global__ void finalize_kernel(float* out) {
    __shared__ float sh[256];
    float local = 0.f;
    for (int i = threadIdx.x; i < BSZ; i += 256) {
        local += 20.0f
               + 0.34657359027997264f * (__log2f(g_sa[i]) + __log2f(g_sb[i]))
               - g_diag[i];
    }
    sh[threadIdx.x] = local;
    __syncthreads();
    for (int s = 128; s > 0; s >>= 1) {
        if (threadIdx.x < s) sh[threadIdx.x] += sh[threadIdx.x + s];
        __syncthreads();
    }
    if (threadIdx.x == 0) out[0] = sh[0] / (float)BSZ;
}

extern "C" void kernel_launch(void* const* d_in, const int* in_sizes, int n_in,
                              void* d_out, int out_size) {
    const float* emb = (const float*)d_in[0];
    const int* links = (const int*)d_in[1];
    (void)in_sizes; (void)n_in; (void)out_size;

    gather_norm<<<1024, 256>>>(emb, links);        // 8192 warps: one per gathered row
    dim3 grid(NT * NT, 3);
    tile_kernel<<<grid, 256>>>();
    finalize_kernel<<<1, 256>>>((float*)d_out);
}

// round 5
// speedup vs baseline: 2.2647x; 2.2647x over previous
#include <cuda_runtime.h>
#include <cuda_bf16.h>
#include <cstdint>

#define BSZ 4096
#define DIM 128
#define NT  32   // 4096 / 128 tiles per dimension

// ---------------- scratch (device globals; no runtime allocation) -----------
__device__ __align__(256) __nv_bfloat16 g_Zi_hi[BSZ * DIM];
__device__ __align__(256) __nv_bfloat16 g_Zi_lo[BSZ * DIM];
__device__ __align__(256) __nv_bfloat16 g_Zj_hi[BSZ * DIM];
__device__ __align__(256) __nv_bfloat16 g_Zj_lo[BSZ * DIM];
__device__ float g_sa[BSZ];     // sum exp(logit-20) rows of logits_a
__device__ float g_sb[BSZ];     // sum exp(logit-20) rows of logits_b
__device__ float g_diag[BSZ];   // logits_ab[i,i]

__device__ __forceinline__ float ex2f(float x) {
    float y;
    asm("ex2.approx.ftz.f32 %0, %1;" : "=f"(y) : "f"(x));
    return y;
}

__device__ __forceinline__ uint32_t smem_u32(const void* p) {
    uint32_t a;
    asm("{ .reg .u64 t; cvta.to.shared.u64 t, %1; cvt.u32.u64 %0, t; }" : "=r"(a) : "l"(p));
    return a;
}

__device__ __forceinline__ void ldm4(uint32_t* r, uint32_t addr) {
    asm volatile("ldmatrix.sync.aligned.m8n8.x4.shared.b16 {%0,%1,%2,%3}, [%4];"
                 : "=r"(r[0]), "=r"(r[1]), "=r"(r[2]), "=r"(r[3]) : "r"(addr));
}

__device__ __forceinline__ void mma_bf16(float* d, const uint32_t* a, const uint32_t* b) {
    asm volatile("mma.sync.aligned.m16n8k16.row.col.f32.bf16.bf16.f32 "
                 "{%0,%1,%2,%3}, {%4,%5,%6,%7}, {%8,%9}, {%0,%1,%2,%3};"
                 : "+f"(d[0]), "+f"(d[1]), "+f"(d[2]), "+f"(d[3])
                 : "r"(a[0]), "r"(a[1]), "r"(a[2]), "r"(a[3]), "r"(b[0]), "r"(b[1]));
}

// ---------------- kernel 1: gather + normalize + fp32 -> bf16 hi/lo split ----
__global__ void gather_norm(const float* __restrict__ emb,
                            const int* __restrict__ links32) {
    int tid  = blockIdx.x * blockDim.x + threadIdx.x;
    if (tid < BSZ) { g_sa[tid] = 0.f; g_sb[tid] = 0.f; }
    int w    = tid >> 5;
    int lane = tid & 31;
    if (w >= 2 * BSZ) return;

    // dtype sniff: int64 links have all-zero odd 32-bit words (values < 2e5)
    bool is64 = true;
#pragma unroll
    for (int j = 0; j < 16; j++) is64 &= (__ldg(&links32[2 * j + 1]) == 0);

    int row   = w >> 1;
    int which = w & 1;  // 0 -> Zi, 1 -> Zj
    int pos   = 2 * row + which;
    long long src;
    if (is64) src = reinterpret_cast<const long long*>(links32)[pos];
    else      src = (long long)links32[pos];

    const float4* p = reinterpret_cast<const float4*>(emb + (size_t)src * DIM);
    float4 v = p[lane];
    float ss = v.x * v.x + v.y * v.y + v.z * v.z + v.w * v.w;
#pragma unroll
    for (int o = 16; o; o >>= 1) ss += __shfl_xor_sync(0xffffffffu, ss, o);
    float inv = 1.0f / fmaxf(sqrtf(ss), 1e-12f);
    float n0 = v.x * inv, n1 = v.y * inv, n2 = v.z * inv, n3 = v.w * inv;

    __nv_bfloat16 h0 = __float2bfloat16_rn(n0), h1 = __float2bfloat16_rn(n1);
    __nv_bfloat16 h2 = __float2bfloat16_rn(n2), h3 = __float2bfloat16_rn(n3);
    __nv_bfloat16 l0 = __float2bfloat16_rn(n0 - __bfloat162float(h0));
    __nv_bfloat16 l1 = __float2bfloat16_rn(n1 - __bfloat162float(h1));
    __nv_bfloat16 l2 = __float2bfloat16_rn(n2 - __bfloat162float(h2));
    __nv_bfloat16 l3 = __float2bfloat16_rn(n3 - __bfloat162float(h3));

    __nv_bfloat16* dh = (which ? g_Zj_hi : g_Zi_hi) + row * DIM + lane * 4;
    __nv_bfloat16* dl = (which ? g_Zj_lo : g_Zi_lo) + row * DIM + lane * 4;
    __nv_bfloat162 hp0; hp0.x = h0; hp0.y = h1;
    __nv_bfloat162 hp1; hp1.x = h2; hp1.y = h3;
    __nv_bfloat162 lp0; lp0.x = l0; lp0.y = l1;
    __nv_bfloat162 lp1; lp1.x = l2; lp1.y = l3;
    reinterpret_cast<__nv_bfloat162*>(dh)[0] = hp0;
    reinterpret_cast<__nv_bfloat162*>(dh)[1] = hp1;
    reinterpret_cast<__nv_bfloat162*>(dl)[0] = lp0;
    reinterpret_cast<__nv_bfloat162*>(dl)[1] = lp1;
}

// ---------------- kernel 2: mma.sync Gram tile + fused softmax epilogue ------
// smem: 4 full 128x128 bf16 tiles [Ah | Al | Bh | Bl], rows padded to 272B
// (128 data + 16 pad) => ldmatrix conflict-free via padding, no XOR swizzle.
#define PB    272            // bytes per smem row
#define BUFB  (128 * PB)     // 34816 bytes per buffer
#define SMEM_DYN (4 * BUFB)  // 139264

__global__ __launch_bounds__(512) void tile_kernel() {
    int type = blockIdx.y;
    int ti = blockIdx.x >> 5;
    int tj = blockIdx.x & 31;
    if (type != 0 && ti > tj) return;   // symmetric matrices: upper triangle only

    extern __shared__ char smem[];
    __shared__ float red_r[4][128];
    __shared__ float red_c[4][128];

    const __nv_bfloat16 *Ah_g, *Al_g, *Bh_g, *Bl_g;
    if (type == 2) { Ah_g = g_Zj_hi; Al_g = g_Zj_lo; } else { Ah_g = g_Zi_hi; Al_g = g_Zi_lo; }
    if (type == 0) { Bh_g = g_Zj_hi; Bl_g = g_Zj_lo; } else { Bh_g = Ah_g; Bl_g = Al_g; }

    const int ib = ti * 128, jb = tj * 128;
    const uint32_t sb = smem_u32(smem);
    int t = threadIdx.x;
    int wid = t >> 5, lid = t & 31;
    int wy = wid & 3, wx = wid >> 2;   // warp tile: rows wy*32..+32, cols wx*32..+32

    // ---- full-tile load: 2048 (row,chunk) pairs per buffer, 4 buffers ----
#pragma unroll
    for (int i = 0; i < 4; i++) {
        int idx = t + 512 * i;          // 0..2047
        int row = idx >> 4, ch = idx & 15;
        uint32_t doff = (uint32_t)(row * PB + ch * 16);
        size_t gA = (size_t)(ib + row) * DIM + ch * 8;
        size_t gB = (size_t)(jb + row) * DIM + ch * 8;
        *reinterpret_cast<uint4*>(smem + doff)            = *reinterpret_cast<const uint4*>(Ah_g + gA);
        *reinterpret_cast<uint4*>(smem + BUFB + doff)     = *reinterpret_cast<const uint4*>(Al_g + gA);
        *reinterpret_cast<uint4*>(smem + 2 * BUFB + doff) = *reinterpret_cast<const uint4*>(Bh_g + gB);
        *reinterpret_cast<uint4*>(smem + 3 * BUFB + doff) = *reinterpret_cast<const uint4*>(Bl_g + gB);
    }
    __syncthreads();

    // ---- ldmatrix base addresses (k-invariant parts) ----
    // A x4: lanes 0-7 rows+0-7 | 8-15 rows+8-15 (same 16B chunk) | 16-31 same rows, chunk+1
    int rowA = lid & 15, ca = lid >> 4;
    // B x4: lanes 0-7 n+0-7 ch | 8-15 n+0-7 ch+1 | 16-23 n+8-15 ch | 24-31 n+8-15 ch+1
    int rowB = (lid & 7) | ((lid >> 1) & 8);
    int cb   = (lid >> 3) & 1;

    uint32_t aBase[2], bBase[2];
#pragma unroll
    for (int mt = 0; mt < 2; mt++)
        aBase[mt] = sb + (uint32_t)((wy * 32 + mt * 16 + rowA) * PB + ca * 16);
#pragma unroll
    for (int n16 = 0; n16 < 2; n16++)
        bBase[n16] = sb + 2 * BUFB + (uint32_t)((wx * 32 + n16 * 16 + rowB) * PB + cb * 16);

    float acc[2][4][4];
#pragma unroll
    for (int mt = 0; mt < 2; mt++)
#pragma unroll
        for (int nt = 0; nt < 4; nt++)
#pragma unroll
            for (int r = 0; r < 4; r++) acc[mt][nt][r] = 0.f;

    // ---- 8 k16 steps x 3 chains (hi*hi + hi*lo + lo*hi) ----
#pragma unroll
    for (int ks = 0; ks < 8; ks++) {
        uint32_t ah[2][4], al[2][4], bh[2][4], bl[2][4];
#pragma unroll
        for (int mt = 0; mt < 2; mt++) {
            ldm4(ah[mt], aBase[mt] + ks * 32);
            ldm4(al[mt], aBase[mt] + BUFB + ks * 32);
        }
#pragma unroll
        for (int n16 = 0; n16 < 2; n16++) {
            ldm4(bh[n16], bBase[n16] + ks * 32);
            ldm4(bl[n16], bBase[n16] + BUFB + ks * 32);
        }
#pragma unroll
        for (int mt = 0; mt < 2; mt++)
#pragma unroll
            for (int nt = 0; nt < 4; nt++)
                mma_bf16(acc[mt][nt], ah[mt], &bh[nt >> 1][(nt & 1) * 2]);
#pragma unroll
        for (int mt = 0; mt < 2; mt++)
#pragma unroll
            for (int nt = 0; nt < 4; nt++)
                mma_bf16(acc[mt][nt], ah[mt], &bl[nt >> 1][(nt & 1) * 2]);
#pragma unroll
        for (int mt = 0; mt < 2; mt++)
#pragma unroll
            for (int nt = 0; nt < 4; nt++)
                mma_bf16(acc[mt][nt], al[mt], &bh[nt >> 1][(nt & 1) * 2]);
    }

    // ---- epilogue: exp + row/col sums ----
    // D frag: lane g=lid>>2, tg=lid&3; reg r: row +8*(r>>1), col tg*2+(r&1)
    const float SC = 20.0f * 1.4426950408889634f;
    bool dt = (ti == tj);
    int g = lid >> 2, tg = lid & 3;

    float rs[2][2] = {{0.f, 0.f}, {0.f, 0.f}};
    float cs[4][2] = {{0.f, 0.f}, {0.f, 0.f}, {0.f, 0.f}, {0.f, 0.f}};

#pragma unroll
    for (int mt = 0; mt < 2; mt++)
#pragma unroll
        for (int nt = 0; nt < 4; nt++)
#pragma unroll
            for (int r = 0; r < 4; r++) {
                int h2 = r >> 1, c2 = r & 1;
                int lr = wy * 32 + mt * 16 + g + h2 * 8;
                int lc = wx * 32 + nt * 8 + tg * 2 + c2;
                float d = acc[mt][nt][r];
                float e = ex2f(fmaf(d, SC, -SC));
                if (dt && lr == lc) {
                    if (type == 0) g_diag[ib + lr] = d * 20.0f;
                    else e = 0.f;                     // mask diag of aa / bb
                }
                rs[mt][h2] += e;
                cs[nt][c2] += e;
            }

    // row sums: reduce over tg (lane bits 0,1)
#pragma unroll
    for (int mt = 0; mt < 2; mt++)
#pragma unroll
        for (int h2 = 0; h2 < 2; h2++) {
            float v = rs[mt][h2];
            v += __shfl_xor_sync(0xffffffffu, v, 1);
            v += __shfl_xor_sync(0xffffffffu, v, 2);
            if (tg == 0) red_r[wx][wy * 32 + mt * 16 + g + h2 * 8] = v;
        }
    // col sums: reduce over g (lane bits 2,3,4)
#pragma unroll
    for (int nt = 0; nt < 4; nt++)
#pragma unroll
        for (int c2 = 0; c2 < 2; c2++) {
            float v = cs[nt][c2];
            v += __shfl_xor_sync(0xffffffffu, v, 4);
            v += __shfl_xor_sync(0xffffffffu, v, 8);
            v += __shfl_xor_sync(0xffffffffu, v, 16);
            if (g == 0) red_c[wy][wx * 32 + nt * 8 + tg * 2 + c2] = v;
        }
    __syncthreads();

    if (t < 128) {
        float s = red_r[0][t] + red_r[1][t] + red_r[2][t] + red_r[3][t];
        atomicAdd((type == 2) ? &g_sb[ib + t] : &g_sa[ib + t], s);
    } else if (t < 256) {
        int c = t - 128;
        float s = red_c[0][c] + red_c[1][c] + red_c[2][c] + red_c[3][c];
        if (type == 0) atomicAdd(&g_sb[jb + c], s);          // S_ba rows = S_ab cols
        else if (ti < tj) atomicAdd((type == 1) ? &g_sa[jb + c] : &g_sb[jb + c], s);
    }
}

// ---------------- kernel 3: final reduction ---------------------------------
__global__ void finalize_kernel(float* out) {
    __shared__ float sh[256];
    float local = 0.f;
    for (int i = threadIdx.x; i < BSZ; i += 256) {
        local += 20.0f
               + 0.34657359027997264f * (__log2f(g_sa[i]) + __log2f(g_sb[i]))
               - g_diag[i];
    }
    sh[threadIdx.x] = local;
    __syncthreads();
    for (int s = 128; s > 0; s >>= 1) {
        if (threadIdx.x < s) sh[threadIdx.x] += sh[threadIdx.x + s];
        __syncthreads();
    }
    if (threadIdx.x == 0) out[0] = sh[0] / (float)BSZ;
}

extern "C" void kernel_launch(void* const* d_in, const int* in_sizes, int n_in,
                              void* d_out, int out_size) {
    const float* emb = (const float*)d_in[0];
    const int* links = (const int*)d_in[1];
    (void)in_sizes; (void)n_in; (void)out_size;

    cudaFuncSetAttribute(tile_kernel, cudaFuncAttributeMaxDynamicSharedMemorySize, SMEM_DYN);

    gather_norm<<<1024, 256>>>(emb, links);
    dim3 grid(NT * NT, 3);
    tile_kernel<<<grid, 512, SMEM_DYN>>>();
    finalize_kernel<<<1, 256>>>((float*)d_out);
}

// round 6
// speedup vs baseline: 4.2844x; 1.8918x over previous
#include <cuda_runtime.h>
#include <cuda_fp16.h>
#include <cstdint>

#define BSZ 4096
#define DIM 128
#define NT  32   // 4096 / 128 tiles per dimension

// ---------------- scratch (device globals; no runtime allocation) -----------
__device__ __align__(256) __half g_Zi_h[BSZ * DIM];   // fp16 normalized rows (links[:,0])
__device__ __align__(256) __half g_Zj_h[BSZ * DIM];   // fp16 normalized rows (links[:,1])
__device__ __align__(256) float  g_Zi_f[BSZ * DIM];   // fp32 normalized (for exact diag)
__device__ __align__(256) float  g_Zj_f[BSZ * DIM];
__device__ float g_sa[BSZ];     // sum exp(logit-20) rows of logits_a
__device__ float g_sb[BSZ];     // sum exp(logit-20) rows of logits_b
__device__ float g_diag[BSZ];   // logits_ab[i,i] (exact fp32)

__device__ __forceinline__ float ex2f(float x) {
    float y;
    asm("ex2.approx.ftz.f32 %0, %1;" : "=f"(y) : "f"(x));
    return y;
}

__device__ __forceinline__ uint32_t smem_u32(const void* p) {
    uint32_t a;
    asm("{ .reg .u64 t; cvta.to.shared.u64 t, %1; cvt.u32.u64 %0, t; }" : "=r"(a) : "l"(p));
    return a;
}

__device__ __forceinline__ void ldm4(uint32_t* r, uint32_t addr) {
    asm volatile("ldmatrix.sync.aligned.m8n8.x4.shared.b16 {%0,%1,%2,%3}, [%4];"
                 : "=r"(r[0]), "=r"(r[1]), "=r"(r[2]), "=r"(r[3]) : "r"(addr));
}

__device__ __forceinline__ void mma_f16(float* d, const uint32_t* a, const uint32_t* b) {
    asm volatile("mma.sync.aligned.m16n8k16.row.col.f32.f16.f16.f32 "
                 "{%0,%1,%2,%3}, {%4,%5,%6,%7}, {%8,%9}, {%0,%1,%2,%3};"
                 : "+f"(d[0]), "+f"(d[1]), "+f"(d[2]), "+f"(d[3])
                 : "r"(a[0]), "r"(a[1]), "r"(a[2]), "r"(a[3]), "r"(b[0]), "r"(b[1]));
}

// ---------------- kernel 1: gather + normalize -> fp32 + fp16 copies --------
__global__ void gather_norm(const float* __restrict__ emb,
                            const int* __restrict__ links32) {
    int tid  = blockIdx.x * blockDim.x + threadIdx.x;
    if (tid < BSZ) { g_sa[tid] = 0.f; g_sb[tid] = 0.f; }
    int w    = tid >> 5;
    int lane = tid & 31;
    if (w >= 2 * BSZ) return;

    // dtype sniff: int64 links have all-zero odd 32-bit words (values < 2e5)
    bool is64 = true;
#pragma unroll
    for (int j = 0; j < 16; j++) is64 &= (__ldg(&links32[2 * j + 1]) == 0);

    int row   = w >> 1;
    int which = w & 1;  // 0 -> Zi, 1 -> Zj
    int pos   = 2 * row + which;
    long long src;
    if (is64) src = reinterpret_cast<const long long*>(links32)[pos];
    else      src = (long long)links32[pos];

    const float4* p = reinterpret_cast<const float4*>(emb + (size_t)src * DIM);
    float4 v = p[lane];
    float ss = v.x * v.x + v.y * v.y + v.z * v.z + v.w * v.w;
#pragma unroll
    for (int o = 16; o; o >>= 1) ss += __shfl_xor_sync(0xffffffffu, ss, o);
    float inv = 1.0f / fmaxf(sqrtf(ss), 1e-12f);
    float n0 = v.x * inv, n1 = v.y * inv, n2 = v.z * inv, n3 = v.w * inv;

    float* df = (which ? g_Zj_f : g_Zi_f) + row * DIM;
    reinterpret_cast<float4*>(df)[lane] = make_float4(n0, n1, n2, n3);

    __half2 h0; h0.x = __float2half_rn(n0); h0.y = __float2half_rn(n1);
    __half2 h1; h1.x = __float2half_rn(n2); h1.y = __float2half_rn(n3);
    __half* dh = (which ? g_Zj_h : g_Zi_h) + row * DIM + lane * 4;
    reinterpret_cast<__half2*>(dh)[0] = h0;
    reinterpret_cast<__half2*>(dh)[1] = h1;
}

// ---------------- kernel 1b: exact fp32 diag: g_diag[i] = 20 * zi.zj --------
__global__ void diag_kernel() {
    int w = (blockIdx.x * blockDim.x + threadIdx.x) >> 5;
    int lane = threadIdx.x & 31;
    if (w >= BSZ) return;
    float4 a = reinterpret_cast<const float4*>(g_Zi_f + (size_t)w * DIM)[lane];
    float4 b = reinterpret_cast<const float4*>(g_Zj_f + (size_t)w * DIM)[lane];
    float d = a.x * b.x + a.y * b.y + a.z * b.z + a.w * b.w;
#pragma unroll
    for (int o = 16; o; o >>= 1) d += __shfl_xor_sync(0xffffffffu, d, o);
    if (lane == 0) g_diag[w] = d * 20.0f;
}

// ---------------- kernel 2: fp16 mma.sync Gram tile + fused epilogue --------
// smem: 2 tiles [A | B], 128 rows x 128 fp16, rows padded to 272B
// (256 data + 16 pad) => conflict-free ldmatrix via padding.
#define PB    272            // bytes per smem row
#define BUFB  (128 * PB)     // 34816 bytes per buffer
#define SMEM_DYN (2 * BUFB)  // 69632

__global__ __launch_bounds__(512, 2) void tile_kernel() {
    int type = blockIdx.y;
    int ti = blockIdx.x >> 5;
    int tj = blockIdx.x & 31;
    if (type != 0 && ti > tj) return;   // symmetric matrices: upper triangle only

    extern __shared__ char smem[];
    __shared__ float red_r[4][128];
    __shared__ float red_c[4][128];

    const __half *A_g, *B_g;
    A_g = (type == 2) ? g_Zj_h : g_Zi_h;
    B_g = (type == 0) ? g_Zj_h : A_g;

    const int ib = ti * 128, jb = tj * 128;
    const uint32_t sb = smem_u32(smem);
    int t = threadIdx.x;
    int wid = t >> 5, lid = t & 31;
    int wy = wid & 3, wx = wid >> 2;   // warp tile: rows wy*32..+32, cols wx*32..+32

    // ---- full-tile load: 2048 16B chunks per buffer ----
#pragma unroll
    for (int i = 0; i < 4; i++) {
        int idx = t + 512 * i;          // 0..2047
        int row = idx >> 4, ch = idx & 15;
        uint32_t doff = (uint32_t)(row * PB + ch * 16);
        *reinterpret_cast<uint4*>(smem + doff) =
            *reinterpret_cast<const uint4*>(A_g + (size_t)(ib + row) * DIM + ch * 8);
        *reinterpret_cast<uint4*>(smem + BUFB + doff) =
            *reinterpret_cast<const uint4*>(B_g + (size_t)(jb + row) * DIM + ch * 8);
    }
    __syncthreads();

    // ---- ldmatrix base addresses (k-invariant parts) ----
    int rowA = lid & 15, ca = lid >> 4;
    int rowB = (lid & 7) | ((lid >> 1) & 8);
    int cb   = (lid >> 3) & 1;

    uint32_t aBase[2], bBase[2];
#pragma unroll
    for (int mt = 0; mt < 2; mt++)
        aBase[mt] = sb + (uint32_t)((wy * 32 + mt * 16 + rowA) * PB + ca * 16);
#pragma unroll
    for (int n16 = 0; n16 < 2; n16++)
        bBase[n16] = sb + BUFB + (uint32_t)((wx * 32 + n16 * 16 + rowB) * PB + cb * 16);

    float acc[2][4][4];
#pragma unroll
    for (int mt = 0; mt < 2; mt++)
#pragma unroll
        for (int nt = 0; nt < 4; nt++)
#pragma unroll
            for (int r = 0; r < 4; r++) acc[mt][nt][r] = 0.f;

    // ---- 8 k16 steps, single fp16 chain ----
#pragma unroll
    for (int ks = 0; ks < 8; ks++) {
        uint32_t a[2][4], b[2][4];
#pragma unroll
        for (int mt = 0; mt < 2; mt++) ldm4(a[mt], aBase[mt] + ks * 32);
#pragma unroll
        for (int n16 = 0; n16 < 2; n16++) ldm4(b[n16], bBase[n16] + ks * 32);
#pragma unroll
        for (int mt = 0; mt < 2; mt++)
#pragma unroll
            for (int nt = 0; nt < 4; nt++)
                mma_f16(acc[mt][nt], a[mt], &b[nt >> 1][(nt & 1) * 2]);
    }

    // ---- epilogue: exp + row/col sums ----
    const float SC = 20.0f * 1.4426950408889634f;
    bool dt = (ti == tj);
    int g = lid >> 2, tg = lid & 3;

    float rs[2][2] = {{0.f, 0.f}, {0.f, 0.f}};
    float cs[4][2] = {{0.f, 0.f}, {0.f, 0.f}, {0.f, 0.f}, {0.f, 0.f}};

#pragma unroll
    for (int mt = 0; mt < 2; mt++)
#pragma unroll
        for (int nt = 0; nt < 4; nt++)
#pragma unroll
            for (int r = 0; r < 4; r++) {
                int h2 = r >> 1, c2 = r & 1;
                int lr = wy * 32 + mt * 16 + g + h2 * 8;
                int lc = wx * 32 + nt * 8 + tg * 2 + c2;
                float e = ex2f(fmaf(acc[mt][nt][r], SC, -SC));
                if (type != 0 && dt && lr == lc) e = 0.f;   // mask diag of aa / bb
                rs[mt][h2] += e;
                cs[nt][c2] += e;
            }

    // row sums: reduce over tg (lane bits 0,1)
#pragma unroll
    for (int mt = 0; mt < 2; mt++)
#pragma unroll
        for (int h2 = 0; h2 < 2; h2++) {
            float v = rs[mt][h2];
            v += __shfl_xor_sync(0xffffffffu, v, 1);
            v += __shfl_xor_sync(0xffffffffu, v, 2);
            if (tg == 0) red_r[wx][wy * 32 + mt * 16 + g + h2 * 8] = v;
        }
    // col sums: reduce over g (lane bits 2,3,4)
#pragma unroll
    for (int nt = 0; nt < 4; nt++)
#pragma unroll
        for (int c2 = 0; c2 < 2; c2++) {
            float v = cs[nt][c2];
            v += __shfl_xor_sync(0xffffffffu, v, 4);
            v += __shfl_xor_sync(0xffffffffu, v, 8);
            v += __shfl_xor_sync(0xffffffffu, v, 16);
            if (g == 0) red_c[wy][wx * 32 + nt * 8 + tg * 2 + c2] = v;
        }
    __syncthreads();

    if (t < 128) {
        float s = red_r[0][t] + red_r[1][t] + red_r[2][t] + red_r[3][t];
        atomicAdd((type == 2) ? &g_sb[ib + t] : &g_sa[ib + t], s);
    } else if (t < 256) {
        int c = t - 128;
        float s = red_c[0][c] + red_c[1][c] + red_c[2][c] + red_c[3][c];
        if (type == 0) atomicAdd(&g_sb[jb + c], s);          // S_ba rows = S_ab cols
        else if (ti < tj) atomicAdd((type == 1) ? &g_sa[jb + c] : &g_sb[jb + c], s);
    }
}

// ---------------- kernel 3: final reduction ---------------------------------
__global__ void finalize_kernel(float* out) {
    __shared__ float sh[256];
    float local = 0.f;
    for (int i = threadIdx.x; i < BSZ; i += 256) {
        local += 20.0f
               + 0.34657359027997264f * (__log2f(g_sa[i]) + __log2f(g_sb[i]))
               - g_diag[i];
    }
    sh[threadIdx.x] = local;
    __syncthreads();
    for (int s = 128; s > 0; s >>= 1) {
        if (threadIdx.x < s) sh[threadIdx.x] += sh[threadIdx.x + s];
        __syncthreads();
    }
    if (threadIdx.x == 0) out[0] = sh[0] / (float)BSZ;
}

extern "C" void kernel_launch(void* const* d_in, const int* in_sizes, int n_in,
                              void* d_out, int out_size) {
    const float* emb = (const float*)d_in[0];
    const int* links = (const int*)d_in[1];
    (void)in_sizes; (void)n_in; (void)out_size;

    cudaFuncSetAttribute(tile_kernel, cudaFuncAttributeMaxDynamicSharedMemorySize, SMEM_DYN);

    gather_norm<<<1024, 256>>>(emb, links);
    diag_kernel<<<512, 256>>>();
    dim3 grid(NT * NT, 3);
    tile_kernel<<<grid, 512, SMEM_DYN>>>();
    finalize_kernel<<<1, 256>>>((float*)d_out);
}

// round 7
// speedup vs baseline: 4.7983x; 1.1199x over previous
#include <cuda_runtime.h>
#include <cuda_fp16.h>
#include <cstdint>

#define BSZ 4096
#define DIM 128
#define NT  32   // 4096 / 128 tiles per dimension
#define N_AB   (NT * NT)            // 1024 full ab tiles
#define N_TRI  (NT * (NT + 1) / 2)  // 528 upper-triangle tiles
#define N_TILES (N_AB + 2 * N_TRI)  // 2080

// ---------------- scratch (device globals; no runtime allocation) -----------
__device__ __align__(256) __half g_Zi_h[BSZ * DIM];   // fp16 normalized rows (links[:,0])
__device__ __align__(256) __half g_Zj_h[BSZ * DIM];   // fp16 normalized rows (links[:,1])
__device__ __align__(256) float  g_Zi_f[BSZ * DIM];   // fp32 normalized (for exact diag)
__device__ __align__(256) float  g_Zj_f[BSZ * DIM];
__device__ float g_sa[BSZ];     // sum exp(logit-20) rows of logits_a
__device__ float g_sb[BSZ];     // sum exp(logit-20) rows of logits_b
__device__ float g_diag[BSZ];   // logits_ab[i,i] (exact fp32)
__device__ float g_loss;        // accumulated loss numerator

__device__ __forceinline__ float ex2f(float x) {
    float y;
    asm("ex2.approx.ftz.f32 %0, %1;" : "=f"(y) : "f"(x));
    return y;
}

__device__ __forceinline__ uint32_t smem_u32(const void* p) {
    uint32_t a;
    asm("{ .reg .u64 t; cvta.to.shared.u64 t, %1; cvt.u32.u64 %0, t; }" : "=r"(a) : "l"(p));
    return a;
}

__device__ __forceinline__ void ldm4(uint32_t* r, uint32_t addr) {
    asm volatile("ldmatrix.sync.aligned.m8n8.x4.shared.b16 {%0,%1,%2,%3}, [%4];"
                 : "=r"(r[0]), "=r"(r[1]), "=r"(r[2]), "=r"(r[3]) : "r"(addr));
}

__device__ __forceinline__ void mma_f16(float* d, const uint32_t* a, const uint32_t* b) {
    asm volatile("mma.sync.aligned.m16n8k16.row.col.f32.f16.f16.f32 "
                 "{%0,%1,%2,%3}, {%4,%5,%6,%7}, {%8,%9}, {%0,%1,%2,%3};"
                 : "+f"(d[0]), "+f"(d[1]), "+f"(d[2]), "+f"(d[3])
                 : "r"(a[0]), "r"(a[1]), "r"(a[2]), "r"(a[3]), "r"(b[0]), "r"(b[1]));
}

// ---------------- kernel 1: gather + normalize -> fp32 + fp16 copies --------
__global__ void gather_norm(const float* __restrict__ emb,
                            const int* __restrict__ links32) {
    int tid  = blockIdx.x * blockDim.x + threadIdx.x;
    if (tid < BSZ) { g_sa[tid] = 0.f; g_sb[tid] = 0.f; }
    if (tid == 0) g_loss = 0.f;
    int w    = tid >> 5;
    int lane = tid & 31;
    if (w >= 2 * BSZ) return;

    // dtype sniff: int64 links have all-zero odd 32-bit words (values < 2e5)
    bool is64 = true;
#pragma unroll
    for (int j = 0; j < 16; j++) is64 &= (__ldg(&links32[2 * j + 1]) == 0);

    int row   = w >> 1;
    int which = w & 1;  // 0 -> Zi, 1 -> Zj
    int pos   = 2 * row + which;
    long long src;
    if (is64) src = reinterpret_cast<const long long*>(links32)[pos];
    else      src = (long long)links32[pos];

    const float4* p = reinterpret_cast<const float4*>(emb + (size_t)src * DIM);
    float4 v = p[lane];
    float ss = v.x * v.x + v.y * v.y + v.z * v.z + v.w * v.w;
#pragma unroll
    for (int o = 16; o; o >>= 1) ss += __shfl_xor_sync(0xffffffffu, ss, o);
    float inv = 1.0f / fmaxf(sqrtf(ss), 1e-12f);
    float n0 = v.x * inv, n1 = v.y * inv, n2 = v.z * inv, n3 = v.w * inv;

    float* df = (which ? g_Zj_f : g_Zi_f) + row * DIM;
    reinterpret_cast<float4*>(df)[lane] = make_float4(n0, n1, n2, n3);

    __half2 h0; h0.x = __float2half_rn(n0); h0.y = __float2half_rn(n1);
    __half2 h1; h1.x = __float2half_rn(n2); h1.y = __float2half_rn(n3);
    __half* dh = (which ? g_Zj_h : g_Zi_h) + row * DIM + lane * 4;
    reinterpret_cast<__half2*>(dh)[0] = h0;
    reinterpret_cast<__half2*>(dh)[1] = h1;
}

// ---------------- kernel 1b: exact fp32 diag: g_diag[i] = 20 * zi.zj --------
__global__ void diag_kernel() {
    int w = (blockIdx.x * blockDim.x + threadIdx.x) >> 5;
    int lane = threadIdx.x & 31;
    if (w >= BSZ) return;
    float4 a = reinterpret_cast<const float4*>(g_Zi_f + (size_t)w * DIM)[lane];
    float4 b = reinterpret_cast<const float4*>(g_Zj_f + (size_t)w * DIM)[lane];
    float d = a.x * b.x + a.y * b.y + a.z * b.z + a.w * b.w;
#pragma unroll
    for (int o = 16; o; o >>= 1) d += __shfl_xor_sync(0xffffffffu, d, o);
    if (lane == 0) g_diag[w] = d * 20.0f;
}

// ---------------- kernel 2: fp16 mma.sync Gram tile + fused epilogue --------
// smem: 2 tiles [A | B], 128 rows x 128 fp16, rows padded to 272B
// => conflict-free ldmatrix via padding.
#define PB    272            // bytes per smem row
#define BUFB  (128 * PB)     // 34816 bytes per buffer
#define SMEM_DYN (2 * BUFB)  // 69632

__global__ __launch_bounds__(512, 2) void tile_kernel() {
    // Dense tile id -> (type, ti, tj). [0,1024): ab full; then two triangles.
    int bid = blockIdx.x;
    int type, ti, tj;
    if (bid < N_AB) {
        type = 0; ti = bid >> 5; tj = bid & 31;
    } else {
        int idx = bid - N_AB;
        type = 1 + (idx >= N_TRI);
        if (idx >= N_TRI) idx -= N_TRI;
        // row i of triangle starts at tri(i) = 32i - i(i-1)/2; row length 32-i
        int i = (int)((65.0f - sqrtf(4225.0f - 8.0f * (float)idx)) * 0.5f);
        // exact fixup against float rounding
        while (i > 0 && (i * NT - i * (i - 1) / 2) > idx) i--;
        while ((i + 1) * NT - (i + 1) * i / 2 <= idx) i++;
        ti = i;
        tj = i + (idx - (i * NT - i * (i - 1) / 2));
    }

    extern __shared__ char smem[];
    __shared__ float red_r[4][128];
    __shared__ float red_c[4][128];

    const __half *A_g, *B_g;
    A_g = (type == 2) ? g_Zj_h : g_Zi_h;
    B_g = (type == 0) ? g_Zj_h : A_g;

    const int ib = ti * 128, jb = tj * 128;
    const uint32_t sb = smem_u32(smem);
    int t = threadIdx.x;
    int wid = t >> 5, lid = t & 31;
    int wy = wid & 3, wx = wid >> 2;   // warp tile: rows wy*32..+32, cols wx*32..+32

    // ---- full-tile load: 2048 16B chunks per buffer ----
#pragma unroll
    for (int i = 0; i < 4; i++) {
        int idx = t + 512 * i;          // 0..2047
        int row = idx >> 4, ch = idx & 15;
        uint32_t doff = (uint32_t)(row * PB + ch * 16);
        *reinterpret_cast<uint4*>(smem + doff) =
            *reinterpret_cast<const uint4*>(A_g + (size_t)(ib + row) * DIM + ch * 8);
        *reinterpret_cast<uint4*>(smem + BUFB + doff) =
            *reinterpret_cast<const uint4*>(B_g + (size_t)(jb + row) * DIM + ch * 8);
    }
    __syncthreads();

    // ---- ldmatrix base addresses (k-invariant parts) ----
    int rowA = lid & 15, ca = lid >> 4;
    int rowB = (lid & 7) | ((lid >> 1) & 8);
    int cb   = (lid >> 3) & 1;

    uint32_t aBase[2], bBase[2];
#pragma unroll
    for (int mt = 0; mt < 2; mt++)
        aBase[mt] = sb + (uint32_t)((wy * 32 + mt * 16 + rowA) * PB + ca * 16);
#pragma unroll
    for (int n16 = 0; n16 < 2; n16++)
        bBase[n16] = sb + BUFB + (uint32_t)((wx * 32 + n16 * 16 + rowB) * PB + cb * 16);

    float acc[2][4][4];
#pragma unroll
    for (int mt = 0; mt < 2; mt++)
#pragma unroll
        for (int nt = 0; nt < 4; nt++)
#pragma unroll
            for (int r = 0; r < 4; r++) acc[mt][nt][r] = 0.f;

    // ---- 8 k16 steps, single fp16 chain ----
#pragma unroll
    for (int ks = 0; ks < 8; ks++) {
        uint32_t a[2][4], b[2][4];
#pragma unroll
        for (int mt = 0; mt < 2; mt++) ldm4(a[mt], aBase[mt] + ks * 32);
#pragma unroll
        for (int n16 = 0; n16 < 2; n16++) ldm4(b[n16], bBase[n16] + ks * 32);
#pragma unroll
        for (int mt = 0; mt < 2; mt++)
#pragma unroll
            for (int nt = 0; nt < 4; nt++)
                mma_f16(acc[mt][nt], a[mt], &b[nt >> 1][(nt & 1) * 2]);
    }

    // ---- epilogue: exp + row/col sums ----
    const float SC = 20.0f * 1.4426950408889634f;
    bool dt = (ti == tj);
    int g = lid >> 2, tg = lid & 3;

    float rs[2][2] = {{0.f, 0.f}, {0.f, 0.f}};
    float cs[4][2] = {{0.f, 0.f}, {0.f, 0.f}, {0.f, 0.f}, {0.f, 0.f}};

#pragma unroll
    for (int mt = 0; mt < 2; mt++)
#pragma unroll
        for (int nt = 0; nt < 4; nt++)
#pragma unroll
            for (int r = 0; r < 4; r++) {
                int h2 = r >> 1, c2 = r & 1;
                int lr = wy * 32 + mt * 16 + g + h2 * 8;
                int lc = wx * 32 + nt * 8 + tg * 2 + c2;
                float e = ex2f(fmaf(acc[mt][nt][r], SC, -SC));
                if (type != 0 && dt && lr == lc) e = 0.f;   // mask diag of aa / bb
                rs[mt][h2] += e;
                cs[nt][c2] += e;
            }

    // row sums: reduce over tg (lane bits 0,1)
#pragma unroll
    for (int mt = 0; mt < 2; mt++)
#pragma unroll
        for (int h2 = 0; h2 < 2; h2++) {
            float v = rs[mt][h2];
            v += __shfl_xor_sync(0xffffffffu, v, 1);
            v += __shfl_xor_sync(0xffffffffu, v, 2);
            if (tg == 0) red_r[wx][wy * 32 + mt * 16 + g + h2 * 8] = v;
        }
    // col sums: reduce over g (lane bits 2,3,4)
#pragma unroll
    for (int nt = 0; nt < 4; nt++)
#pragma unroll
        for (int c2 = 0; c2 < 2; c2++) {
            float v = cs[nt][c2];
            v += __shfl_xor_sync(0xffffffffu, v, 4);
            v += __shfl_xor_sync(0xffffffffu, v, 8);
            v += __shfl_xor_sync(0xffffffffu, v, 16);
            if (g == 0) red_c[wy][wx * 32 + nt * 8 + tg * 2 + c2] = v;
        }
    __syncthreads();

    if (t < 128) {
        float s = red_r[0][t] + red_r[1][t] + red_r[2][t] + red_r[3][t];
        atomicAdd((type == 2) ? &g_sb[ib + t] : &g_sa[ib + t], s);
    } else if (t < 256) {
        int c = t - 128;
        float s = red_c[0][c] + red_c[1][c] + red_c[2][c] + red_c[3][c];
        if (type == 0) atomicAdd(&g_sb[jb + c], s);          // S_ba rows = S_ab cols
        else if (ti < tj) atomicAdd((type == 1) ? &g_sa[jb + c] : &g_sb[jb + c], s);
    }
}

// ---------------- kernel 3a: parallel partial loss reduction ----------------
__global__ void finalize_partial() {
    __shared__ float sh[256];
    int t = threadIdx.x;
    float local = 0.f;
    for (int i = blockIdx.x * 256 + t; i < BSZ; i += gridDim.x * 256) {
        local += 20.0f
               + 0.34657359027997264f * (__log2f(g_sa[i]) + __log2f(g_sb[i]))
               - g_diag[i];
    }
    sh[t] = local;
    __syncthreads();
    for (int s = 128; s > 0; s >>= 1) {
        if (t < s) sh[t] += sh[t + s];
        __syncthreads();
    }
    if (t == 0) atomicAdd(&g_loss, sh[0]);
}

// ---------------- kernel 3b: writeout ---------------------------------------
__global__ void finalize_write(float* out) {
    out[0] = g_loss / (float)BSZ;
}

extern "C" void kernel_launch(void* const* d_in, const int* in_sizes, int n_in,
                              void* d_out, int out_size) {
    const float* emb = (const float*)d_in[0];
    const int* links = (const int*)d_in[1];
    (void)in_sizes; (void)n_in; (void)out_size;

    cudaFuncSetAttribute(tile_kernel, cudaFuncAttributeMaxDynamicSharedMemorySize, SMEM_DYN);

    gather_norm<<<1024, 256>>>(emb, links);
    diag_kernel<<<512, 256>>>();
    tile_kernel<<<N_TILES, 512, SMEM_DYN>>>();
    finalize_partial<<<16, 256>>>();
    finalize_write<<<1, 1>>>((float*)d_out);
}